// round 10
// baseline (speedup 1.0000x reference)
#include <cuda_runtime.h>
#include <math.h>

// Geometry: N_LAYERS=12, H=12, Vq(L)=2+13L, Vm=Vq+12, layer size 37*Vq+12
#define NP      32936     // P_TOTAL
#define NLM     32778     // _LM_BASE
#define NV      158       // V_TOTAL
#define NLAY    12
#define NWORDS  1030      // ceil(NP/32)
#define NTHR    256
#define NCHUNK  258       // ceil(NP/128)
#define PSTRIDE (NWORDS + 2)

__constant__ int c_lbase[NLAY] = {0, 86, 653, 1701, 3230, 5240, 7731,
                                  10703, 14156, 18090, 22505, 27401};

__device__ __align__(16) float g_pa[NP + 8];   // p*r + 0.5
__device__ __align__(16) float g_rw[NP + 8];   // 1/window

// ---------------------------------------------------------------------------
__global__ void precompute_kernel(const float* __restrict__ sp) {
    int i = blockIdx.x * blockDim.x + threadIdx.x;
    if (i >= NP) return;
    double pd = 1.0 / (1.0 + exp(-(double)sp[i]));
    float p = (float)pd;
    float w = p * (1.0f - p);
    float pp = w * p + (1.0f - w) * p;      // value == p (matches ref)
    float r  = __fdiv_rn(1.0f, w);
    g_rw[i] = r;
    g_pa[i] = fmaf(pp, r, 0.5f);            // mask = sat(A - u*r)
}

// ---------------------------------------------------------------------------
__device__ __forceinline__ unsigned ext32(const unsigned* P, int s) {
    return __funnelshift_r(P[s >> 5], P[(s >> 5) + 1], s & 31);
}
__device__ __forceinline__ unsigned lenmask(int n) {        // n in (0,32]
    return (n >= 32) ? 0xffffffffu : ((1u << n) - 1u);
}
__device__ __forceinline__ int getbit(const unsigned* B, int p) {
    return (B[p >> 5] >> (p & 31)) & 1;
}
// spread low 8 bits to bit positions 0,4,8,...,28
__device__ __forceinline__ unsigned spread8(unsigned x) {
    x &= 0xFFu;
    x = (x | (x << 12)) & 0x000F000Fu;
    x = (x | (x << 6))  & 0x03030303u;
    x = (x | (x << 3))  & 0x11111111u;
    return x;
}

// ---------------------------------------------------------------------------
// Per-row graph phases (run by one warp each; pos/R/O row-private)
__device__ __forceinline__ void reach_fwd(const unsigned* pos, unsigned* sR, int lane) {
    for (int L = 0; L < NLAY; L++) {
        const int Vq = 2 + 13 * L, b = c_lbase[L];
        unsigned acc1 = 0;
        {
            int s = b + lane * Vq;
            #pragma unroll
            for (int k = 0; k < 5; k++)
                if (32 * k < Vq) acc1 |= ext32(pos, s + 32 * k) & sR[k];
        }
        bool a2 = false;
        if (lane < 4) {
            unsigned acc2 = 0;
            int s = b + (32 + lane) * Vq;
            #pragma unroll
            for (int k = 0; k < 5; k++)
                if (32 * k < Vq) acc2 |= ext32(pos, s + 32 * k) & sR[k];
            a2 = acc2 != 0;
        }
        unsigned b1 = __ballot_sync(0xffffffffu, acc1 != 0);
        unsigned b2 = __ballot_sync(0xffffffffu, a2);
        if (lane == 0) {
            #pragma unroll
            for (int h = 0; h < 12; h++) {
                unsigned q = (b1 >> h) & 1u;
                unsigned kk = (b1 >> (12 + h)) & 1u;
                unsigned v = (24 + h < 32) ? ((b1 >> (24 + h)) & 1u)
                                           : ((b2 >> (h - 8)) & 1u);
                if (q & kk & v) { int p = Vq + h; sR[p >> 5] |= 1u << (p & 31); }
            }
        }
        __syncwarp();
        const int Vm = Vq + 12, sm = b + 36 * Vq;
        bool am = false;
        if (lane < 5 && 32 * lane < Vm)
            am = (ext32(pos, sm + 32 * lane) & sR[lane]) != 0;
        unsigned bm = __ballot_sync(0xffffffffu, am);
        if (lane == 0 && bm) sR[Vm >> 5] |= 1u << (Vm & 31);
        __syncwarp();
    }
}

__device__ __forceinline__ void reach_bwd(const unsigned* pos, const unsigned* sR,
                                          unsigned* sO, int lane) {
    if (lane < 5) sO[lane] = ext32(pos, NLM + 32 * lane) & sR[lane] & lenmask(NV - 32 * lane);
    __syncwarp();
    for (int L = NLAY - 1; L >= 0; L--) {
        const int Vq = 2 + 13 * L, b = c_lbase[L], Vm = Vq + 12;
        int obm = getbit(sO, Vm) & getbit(sR, Vm);
        __syncwarp();
        if (obm && lane < 5 && 32 * lane < Vm)
            sO[lane] |= ext32(pos, b + 36 * Vq + 32 * lane) & sR[lane] & lenmask(Vm - 32 * lane);
        __syncwarp();
        unsigned wk[5] = {0, 0, 0, 0, 0};
        {
            int h = Vq + (lane % 12);
            if (getbit(sR, h) & getbit(sO, h)) {
                int s = b + lane * Vq;
                #pragma unroll
                for (int k = 0; k < 5; k++)
                    if (32 * k < Vq) wk[k] = ext32(pos, s + 32 * k) & sR[k] & lenmask(Vq - 32 * k);
            }
        }
        if (lane < 4) {
            int h = Vq + ((32 + lane) % 12);
            if (getbit(sR, h) & getbit(sO, h)) {
                int s = b + (32 + lane) * Vq;
                #pragma unroll
                for (int k = 0; k < 5; k++)
                    if (32 * k < Vq) wk[k] |= ext32(pos, s + 32 * k) & sR[k] & lenmask(Vq - 32 * k);
            }
        }
        #pragma unroll
        for (int k = 0; k < 5; k++) {
            unsigned red = __reduce_or_sync(0xffffffffu, wk[k]);
            if (lane == 0) sO[k] |= red;
        }
        __syncwarp();
    }
}

// ---------------------------------------------------------------------------
__global__ __launch_bounds__(NTHR) void mask_kernel(const float* __restrict__ unif,
                                                    float* __restrict__ out, int bz) {
    __shared__ unsigned posbuf[2 * PSTRIDE];
    __shared__ unsigned sR[16];
    __shared__ unsigned sO[16];

    const int t = threadIdx.x, warp = t >> 5, lane = t & 31;
    const int row0 = 2 * blockIdx.x;
    const bool has2 = (row0 + 1) < bz;
    const size_t off0 = (size_t)row0 * NP;
    const size_t off1 = off0 + (has2 ? NP : 0);

    const float4* u40 = (const float4*)(unif + off0);
    const float4* u41 = (const float4*)(unif + off1);
    float4*       o40 = (float4*)(out + off0);
    float4*       o41 = (float4*)(out + off1);
    const float4* pa4 = (const float4*)g_pa;
    const float4* rw4 = (const float4*)g_rw;
    float*        orow0 = out + off0;
    float*        orow1 = out + off1;

    if (t < 16) { sR[t] = ((t & 7) == 0) ? 3u : 0u; sO[t] = 0u; }
    if (t == 0) {
        posbuf[NWORDS] = 0u; posbuf[NWORDS + 1] = 0u;
        posbuf[PSTRIDE + NWORDS] = 0u; posbuf[PSTRIDE + NWORDS + 1] = 0u;
    }

    // ---- Pass 1: 2 rows, shared table loads, sat-FMA, ballots -> bitsets ----
    for (int c = warp; c < NCHUNK; c += NTHR / 32) {
        int f = 32 * c + lane;
        bool q0 = false, q1 = false, q2 = false, q3 = false;
        bool s0 = false, s1 = false, s2 = false, s3 = false;
        if (4 * f < NP) {
            float4 a = __ldg(pa4 + f);
            float4 r = __ldg(rw4 + f);
            float4 u0 = __ldcs(u40 + f);
            float4 u1 = __ldcs(u41 + f);
            float m0 = __saturatef(fmaf(-u0.x, r.x, a.x));
            float m1 = __saturatef(fmaf(-u0.y, r.y, a.y));
            float m2 = __saturatef(fmaf(-u0.z, r.z, a.z));
            float m3 = __saturatef(fmaf(-u0.w, r.w, a.w));
            float n0 = __saturatef(fmaf(-u1.x, r.x, a.x));
            float n1 = __saturatef(fmaf(-u1.y, r.y, a.y));
            float n2 = __saturatef(fmaf(-u1.z, r.z, a.z));
            float n3 = __saturatef(fmaf(-u1.w, r.w, a.w));
            __stcs(o40 + f, make_float4(m0, m1, m2, m3));
            if (has2) __stcs(o41 + f, make_float4(n0, n1, n2, n3));
            q0 = m0 > 0.0f; q1 = m1 > 0.0f; q2 = m2 > 0.0f; q3 = m3 > 0.0f;
            s0 = n0 > 0.0f; s1 = n1 > 0.0f; s2 = n2 > 0.0f; s3 = n3 > 0.0f;
        }
        unsigned a0 = __ballot_sync(0xffffffffu, q0);
        unsigned a1 = __ballot_sync(0xffffffffu, q1);
        unsigned a2 = __ballot_sync(0xffffffffu, q2);
        unsigned a3 = __ballot_sync(0xffffffffu, q3);
        unsigned b0 = __ballot_sync(0xffffffffu, s0);
        unsigned b1 = __ballot_sync(0xffffffffu, s1);
        unsigned b2 = __ballot_sync(0xffffffffu, s2);
        unsigned b3 = __ballot_sync(0xffffffffu, s3);
        if (lane < 8) {
            int sub = lane & 3, rs = lane >> 2;
            unsigned x0 = rs ? b0 : a0, x1 = rs ? b1 : a1;
            unsigned x2 = rs ? b2 : a2, x3 = rs ? b3 : a3;
            int sh = 8 * sub;
            unsigned w = spread8(x0 >> sh)
                       | (spread8(x1 >> sh) << 1)
                       | (spread8(x2 >> sh) << 2)
                       | (spread8(x3 >> sh) << 3);
            int wi = 4 * c + sub;
            if (wi < NWORDS) posbuf[rs * PSTRIDE + wi] = w;
        }
    }
    __syncthreads();

    // ---- Graph phases: warp 0 -> row 0, warp 1 -> row 1 (concurrent) ----
    if (warp < 2 && (warp == 0 || has2)) {
        unsigned* pos = posbuf + warp * PSTRIDE;
        unsigned* R   = sR + 8 * warp;
        unsigned* O   = sO + 8 * warp;
        reach_fwd(pos, R, lane);
        reach_bwd(pos, R, O, lane);
    }
    __syncthreads();

    // ---- Single final prune per row: kill = pos & ~(keepR & keepO) ----
    const int NTASK = has2 ? 908 : 454;
    for (int g = t; g < NTASK; g += NTHR) {
        int rs = (g >= 454) ? 1 : 0;
        int gg = g - 454 * rs;
        const unsigned* pos = posbuf + rs * PSTRIDE;
        const unsigned* R   = sR + 8 * rs;
        const unsigned* O   = sO + 8 * rs;
        float* orow = rs ? orow1 : orow0;
        if (gg < 444) {
            int L = gg / 37, r = gg % 37;
            int Vq = 2 + 13 * L, b = c_lbase[L];
            int s, len, hv;
            if (r < 36) { s = b + r * Vq; len = Vq; hv = Vq + (r % 12); }
            else        { s = b + 36 * Vq; len = Vq + 12; hv = Vq + 12; }
            int hk = getbit(R, hv) & getbit(O, hv);
            for (int k = 0; 32 * k < len; k++) {
                unsigned keep = hk ? (R[k] & O[k]) : 0u;
                unsigned kill = ext32(pos, s + 32 * k) & ~keep & lenmask(len - 32 * k);
                while (kill) {
                    int bp = __ffs(kill) - 1; kill &= kill - 1;
                    orow[s + 32 * k + bp] = 0.0f;
                }
            }
        } else if (gg < 449) {
            int k = gg - 444;
            int s = NLM + 32 * k;
            unsigned kill = ext32(pos, s) & ~(R[k] & O[k]) & lenmask(NV - 32 * k);
            while (kill) {
                int bp = __ffs(kill) - 1; kill &= kill - 1;
                orow[s + bp] = 0.0f;
            }
        }
    }
}

// ---------------------------------------------------------------------------
extern "C" void kernel_launch(void* const* d_in, const int* in_sizes, int n_in,
                              void* d_out, int out_size) {
    const float* sp   = (const float*)d_in[0];
    const float* unif = (const float*)d_in[1];
    float*       out  = (float*)d_out;
    int bz = in_sizes[1] / NP;

    precompute_kernel<<<(NP + 255) / 256, 256>>>(sp);
    mask_kernel<<<(bz + 1) / 2, NTHR>>>(unif, out, bz);
}